// round 11
// baseline (speedup 1.0000x reference)
#include <cuda_runtime.h>
#include <cstdint>

#define FULLMASK 0xffffffffu
#define CAP 9216          // hard upper bound on candidates per (b,g) at L0
#define LBLOCK 512
#define NWARPS (LBLOCK/32)
#define LEVEL_BLOCKS 1536
#define DENSE_BLOCKS 168          // 168*512 = 86016 float4 = 344064 floats
#define TOTAL_BLOCKS (LEVEL_BLOCKS + DENSE_BLOCKS)
#define T3BITS 0x40400000u        // __float_as_uint(3.0f)

// ---------------- global scratch (no allocs allowed) ----------------
__device__ double g_reg, g_cls, g_obj;
__device__ unsigned long long g_pc, g_objt;
__device__ unsigned int g_done;
__device__ unsigned int g_epoch = 1u;
__device__ unsigned int g_tag[344064];

// stable softplus, matches jax.nn.softplus
__device__ __forceinline__ float sp(float x){
    return fmaxf(x, 0.0f) + log1pf(expf(-fabsf(x)));
}

__global__ __launch_bounds__(LBLOCK, 3) void level_all(
    const float* __restrict__ reg0, const float* __restrict__ cls0,
    const float* __restrict__ reg1, const float* __restrict__ cls1,
    const float* __restrict__ reg2, const float* __restrict__ cls2,
    const float* __restrict__ o0,   const float* __restrict__ o1,
    const float* __restrict__ o2,
    const float* __restrict__ gt,
    float* __restrict__ out)
{
    extern __shared__ unsigned int smem_raw[];
    unsigned int*      sdist  = smem_raw;                    // CAP u32
    unsigned int*      sh_hist= smem_raw + CAP;              // 256 u32
    unsigned short*    sidx   = (unsigned short*)(smem_raw + CAP + 256); // CAP u16
    __shared__ unsigned int srow[128];
    __shared__ unsigned int sh_ns, sh_nb, sh_sel, sh_newk, sh_selcnt;
    __shared__ unsigned int sh_D, sh_Ti;
    __shared__ float s_reg, s_cls, s_obj; __shared__ int s_cnt, s_ot;

    const int tid  = threadIdx.x;
    const int lane = tid & 31;
    const int warpid = tid >> 5;
    const unsigned ep = g_epoch;

    auto finish = [&](){
        __syncthreads();
        if (tid==0){
            __threadfence();
            unsigned ticket = atomicAdd(&g_done, 1u);
            if (ticket == TOTAL_BLOCKS-1){
                double reg = atomicAdd(&g_reg, 0.0);
                double cls = atomicAdd(&g_cls, 0.0);
                double obj = atomicAdd(&g_obj, 0.0);
                double pcv = (double)atomicAdd(&g_pc, 0ull);
                double otv = (double)atomicAdd(&g_objt, 0ull);
                double pc = pcv < 1.0 ? 1.0 : pcv;
                double nc = 344064.0 - otv; if (nc < 1.0) nc = 1.0;
                out[0] = (float)(reg/pc + obj/(pc+nc) + cls/pc);
                g_reg = 0.0; g_cls = 0.0; g_obj = 0.0;
                g_pc = 0ull; g_objt = 0ull;
                g_epoch = ep + 1u;
                __threadfence();
                g_done = 0u;
            }
        }
    };

    // ---------- dense obj blocks (tail-filling) ----------
    if (blockIdx.x >= LEVEL_BLOCKS){
        int v = (blockIdx.x - LEVEL_BLOCKS)*LBLOCK + tid;   // < 86016
        int i = v*4;
        const float* p; int local;
        if (i < 262144){ p=o0; local=i; }
        else if (i < 327680){ p=o1; local=i-262144; }
        else { p=o2; local=i-327680; }
        float4 x = *(const float4*)(p + local);
        float sum = sp(x.x)+sp(x.y)+sp(x.z)+sp(x.w);
        for (int off=16;off;off>>=1)
            sum += __shfl_xor_sync(FULLMASK,sum,off);
        __shared__ float s_sum;
        if (tid==0) s_sum = 0.f;
        __syncthreads();
        if (lane==0) atomicAdd(&s_sum, sum);
        __syncthreads();
        if (tid==0) atomicAdd(&g_obj, (double)s_sum);
        finish();
        return;
    }

    const int lv   = blockIdx.x >> 9;
    const int pair = blockIdx.x & 511;
    const int b    = pair >> 5;            // Ng = 32

    int W, logW, lvbase; float stride;
    const float *preg, *pcls, *pobj;
    if (lv==0){ W=128; logW=7; lvbase=0;      stride= 8.f; preg=reg0; pcls=cls0; pobj=o0; }
    else if (lv==1){ W=64; logW=6; lvbase=262144; stride=16.f; preg=reg1; pcls=cls1; pobj=o1; }
    else       { W=32; logW=5; lvbase=327680; stride=32.f; preg=reg2; pcls=cls2; pobj=o2; }
    const int H  = W;
    const int HW = 1 << (2*logW);

    if (tid==0){ sh_ns=0; sh_nb=0; s_reg=0.f; s_cls=0.f; s_obj=0.f; s_cnt=0; s_ot=0; }
    __syncthreads();

    const float* t = gt + (size_t)pair * 6;
    const float Ax=t[0],Ay=t[1],Bx=t[2],By=t[3],Cx=t[4],Cy=t[5];

    const float c1a = Ay-By, c1b = -(Ax-Bx), c1c = -Bx*(Ay-By) + By*(Ax-Bx);
    const float c2a = By-Cy, c2b = -(Bx-Cx), c2c = -Cx*(By-Cy) + Cy*(Bx-Cx);
    const float c3a = Cy-Ay, c3b = -(Cx-Ax), c3c = -Ax*(Cy-Ay) + Ay*(Cx-Ax);
    const float v0x=Bx-Ax, v0y=By-Ay, r0=1.0f/(v0x*v0x+v0y*v0y+1e-9f);
    const float v1x=Cx-Bx, v1y=Cy-By, r1=1.0f/(v1x*v1x+v1y*v1y+1e-9f);
    const float v2x=Ax-Cx, v2y=Ay-Cy, r2=1.0f/(v2x*v2x+v2y*v2y+1e-9f);

    float xmn = fminf(Ax,fminf(Bx,Cx)) - 3.0f;
    float xmx = fmaxf(Ax,fmaxf(Bx,Cx)) + 3.0f;
    float ymn = fminf(Ay,fminf(By,Cy)) - 3.0f;
    float ymx = fmaxf(Ay,fmaxf(By,Cy)) + 3.0f;
    float inv = 1.0f/stride;
    int w0 = max(0,   (int)floorf(xmn*inv - 0.5f) - 1);
    int w1 = min(W-1, (int)ceilf (xmx*inv - 0.5f) + 1);
    int h0 = max(0,   (int)floorf(ymn*inv - 0.5f) - 1);
    int h1 = min(H-1, (int)ceilf (ymx*inv - 0.5f) + 1);
    int winH = h1 - h0 + 1; if (w1 < w0) winH = 0;

    // ---- phase 0: per-row candidate interval via strip clipping ----
    if (tid < winH){
        float py = (h0+tid+0.5f)*stride;
        float ylo = py - 3.0f, yhi = py + 3.0f;
        float xa = 1e30f, xb = -1e30f;
        auto edge = [&](float Px,float Py,float Qx,float Qy){
            float vy = Qy-Py;
            float t0 = 0.f, t1 = 1.f;
            if (fabsf(vy) > 1e-9f){
                float rv = 1.0f/vy;
                float ta = (ylo-Py)*rv, tb = (yhi-Py)*rv;
                t0 = fmaxf(0.f, fminf(ta,tb));
                t1 = fminf(1.f, fmaxf(ta,tb));
                if (t0 > t1) return;
            } else {
                if (Py < ylo || Py > yhi) return;
            }
            float vx = Qx-Px;
            float x0 = Px + t0*vx, x1 = Px + t1*vx;
            xa = fminf(xa, fminf(x0,x1));
            xb = fmaxf(xb, fmaxf(x0,x1));
        };
        edge(Ax,Ay,Bx,By); edge(Bx,By,Cx,Cy); edge(Cx,Cy,Ax,Ay);
        int clo = w0, ncols = 0;
        if (xb >= xa){
            xa -= 3.0f + stride; xb += 3.0f + stride;
            clo     = (int)floorf(xa*inv - 0.5f) - 1;
            int chi = (int)ceilf (xb*inv - 0.5f) + 1;
            clo = max(clo, w0); chi = min(chi, w1);
            ncols = chi - clo + 1;
            if (ncols < 0){ ncols = 0; clo = w0; }
        }
        srow[tid] = (unsigned)clo | ((unsigned)ncols << 16);
    }
    __syncthreads();

    // ---- phase 1: warp-per-row geometry; partitioned store:
    //      dist<=3 ("small") ascending from 0, dist>3 ("big") descending from CAP.
    for (int rr = warpid; rr < winH; rr += NWARPS){
        unsigned pk = srow[rr];
        int clo   = pk & 0xFFFFu;
        int ncols = pk >> 16;
        int hh = h0 + rr;
        float py = (hh+0.5f)*stride;
        float d1r = py*c1b + c1c;
        float d2r = py*c2b + c2c;
        float d3r = py*c3b + c3c;
        float wy0 = py-Ay, wy1 = py-By, wy2 = py-Cy;
        float ky0 = wy0*v0y, ky1 = wy1*v1y, ky2 = wy2*v2y;
        for (int c0 = 0; c0 < ncols; c0 += 32){
            int cc = c0 + lane;
            bool valid = cc < ncols;
            int ww = clo + cc;
            unsigned int dv = 0, iv = 0; bool cand = false;
            if (valid){
                float px = (ww+0.5f)*stride;
                float d1 = px*c1a + d1r;
                float d2 = px*c2a + d2r;
                float d3 = px*c3a + d3r;
                bool hneg = (d1<0.f)||(d2<0.f)||(d3<0.f);
                bool hpos = (d1>0.f)||(d2>0.f)||(d3>0.f);
                bool inside = !(hneg&&hpos);
                float wx, tt, dx, dy;
                wx=px-Ax; tt=fminf(fmaxf((wx*v0x+ky0)*r0,0.f),1.f);
                dx=wx-tt*v0x; dy=wy0-tt*v0y; float q0=dx*dx+dy*dy;
                wx=px-Bx; tt=fminf(fmaxf((wx*v1x+ky1)*r1,0.f),1.f);
                dx=wx-tt*v1x; dy=wy1-tt*v1y; float q1=dx*dx+dy*dy;
                wx=px-Cx; tt=fminf(fmaxf((wx*v2x+ky2)*r2,0.f),1.f);
                dx=wx-tt*v2x; dy=wy2-tt*v2y; float q2=dx*dx+dy*dy;
                float dist = sqrtf(fminf(q0,fminf(q1,q2)) + 1e-12f);
                if (inside || dist<=3.0f){
                    cand = true;
                    dv = __float_as_uint(dist);
                    iv = (unsigned)((hh<<logW)|ww);
                }
            }
            bool issmall = cand && (dv <= T3BITS);
            unsigned balS = __ballot_sync(FULLMASK, issmall);
            unsigned balB = __ballot_sync(FULLMASK, cand && !issmall);
            unsigned baseS = 0, baseB = 0;
            if (lane==0){
                if (balS) baseS = atomicAdd(&sh_ns, (unsigned)__popc(balS));
                if (balB) baseB = atomicAdd(&sh_nb, (unsigned)__popc(balB));
            }
            baseS = __shfl_sync(FULLMASK, baseS, 0);
            baseB = __shfl_sync(FULLMASK, baseB, 0);
            if (cand){
                unsigned lt = (1u<<lane)-1u;
                if (issmall){
                    unsigned pos = baseS + __popc(balS & lt);
                    if (pos < CAP){ sdist[pos]=dv; sidx[pos]=(unsigned short)iv; }
                } else {
                    unsigned pos = baseB + __popc(balB & lt);
                    int q = CAP-1-(int)pos;
                    if (q >= 0){ sdist[q]=dv; sidx[q]=(unsigned short)iv; }
                }
            }
        }
    }
    __syncthreads();
    const int ns = min((int)sh_ns, CAP);
    const int nb = min((int)sh_nb, CAP);
    const int n  = ns + nb;
    const bool accept_all = (n <= 96);

    // warp-0 scan+pick over 256 bins; writes sh_sel/sh_newk/sh_selcnt
    auto scanpick = [&](int k){
        if (tid < 32){
            unsigned v[8]; unsigned run=0;
            #pragma unroll
            for (int u=0;u<8;u++){ run += sh_hist[lane*8+u]; v[u]=run; }
            unsigned p = run;
            #pragma unroll
            for (int off=1;off<32;off<<=1){
                unsigned nn = __shfl_up_sync(FULLMASK,p,off);
                if (lane>=off) p += nn;
            }
            unsigned excl = p - run;
            #pragma unroll
            for (int u=0;u<8;u++){
                unsigned cum  = excl + v[u];
                unsigned prev = excl + (u? v[u-1] : 0u);
                if (cum >= (unsigned)k && prev < (unsigned)k){
                    sh_sel = lane*8+u; sh_newk = k - prev; sh_selcnt = cum - prev;
                }
            }
        }
    };

    // region radix select: k-th smallest (dist, idx) over sdist/sidx[base..base+cnt)
    // results in sh_D / sh_Ti
    auto do_select = [&](int base, int cnt, int k){
        if (tid==0){ sh_D = 0xFFFFFFFFu; sh_Ti = 0xFFFFu; }
        unsigned pref = 0;
        bool done = false;
        for (int shift=24; shift>=0 && !done; shift-=8){
            if (tid < 256) sh_hist[tid] = 0;
            __syncthreads();
            for (int j0=0; j0<cnt; j0+=LBLOCK){
                int j = j0 + tid;
                unsigned bin = 0xFFFFFFFFu;
                if (j < cnt){
                    unsigned dv = sdist[base+j];
                    if (shift==24 || (dv>>(shift+8)) == pref)
                        bin = (dv>>shift)&0xFF;
                }
                unsigned mm = __match_any_sync(FULLMASK, bin);
                if (bin != 0xFFFFFFFFu && lane == (__ffs(mm)-1))
                    atomicAdd(&sh_hist[bin], (unsigned)__popc(mm));
            }
            __syncthreads();
            scanpick(k);
            __syncthreads();
            unsigned sel = sh_sel; k = (int)sh_newk; unsigned ceq = sh_selcnt;
            pref = (pref<<8) | sel;
            if (ceq == 1u){
                for (int j=tid; j<cnt; j+=LBLOCK)
                    if ((sdist[base+j]>>shift) == pref) sh_D = sdist[base+j];
                done = true;
            } else if (shift==0){
                if (tid==0) sh_D = pref;
                if ((unsigned)k != ceq){
                    unsigned ipref = 0;
                    for (int s2_=8; s2_>=0; s2_-=8){
                        __syncthreads();
                        if (tid < 256) sh_hist[tid] = 0;
                        __syncthreads();
                        for (int j0=0; j0<cnt; j0+=LBLOCK){
                            int j = j0 + tid;
                            unsigned bin = 0xFFFFFFFFu;
                            if (j < cnt && sdist[base+j] == pref){
                                unsigned ivv = sidx[base+j];
                                if (s2_==8 || (ivv>>8) == ipref)
                                    bin = (ivv>>s2_)&0xFF;
                            }
                            unsigned mm = __match_any_sync(FULLMASK, bin);
                            if (bin != 0xFFFFFFFFu && lane == (__ffs(mm)-1))
                                atomicAdd(&sh_hist[bin], (unsigned)__popc(mm));
                        }
                        __syncthreads();
                        scanpick(k);
                        __syncthreads();
                        ipref = (ipref<<8) | sh_sel; k = (int)sh_newk;
                    }
                    if (tid==0) sh_Ti = ipref;
                }
                done = true;
            }
        }
        __syncthreads();
    };

    // ---- phase 2: region-restricted selection ----
    // nsmall>=96  -> threshold lives in small region; big region all-rejected.
    // nsmall<96   -> all small accepted; select (96-ns) within big region.
    bool selS = false, selB = false;
    if (!accept_all){
        if (ns >= 96){ selS = true; do_select(0, ns, 96); }
        else         { selB = true; do_select(CAP-nb, nb, 96-ns); }
    }
    __syncthreads();
    const unsigned D  = sh_D;
    const unsigned Ti = sh_Ti;

    // ---- phase 3: accumulate over accepted candidates; claim cells ----
    float regsum=0.f, clssum=0.f, objsum=0.f; int cnt=0, ot=0;
    const float* rbase = preg + (size_t)b*6*HW;
    const float* cbase = pcls + (size_t)b*HW;
    const float* obase = pobj + (size_t)b*HW;
    unsigned int* tbase = g_tag + lvbase + b*HW;

    auto acc = [&](int jj, bool thr){
        unsigned dv = sdist[jj];
        unsigned ivv = sidx[jj];
        if (thr){
            if (dv > D) return;
            if (dv == D && ivv > Ti) return;
        }
        int idx = (int)ivv;
        int hh = idx >> logW, ww = idx & (W-1);
        float px=(ww+0.5f)*stride, py=(hh+0.5f)*stride;
        float g0x=(Ax-px)*inv, g0y=(Ay-py)*inv;
        float g1x=(Bx-px)*inv, g1y=(By-py)*inv;
        float g2x=(Cx-px)*inv, g2y=(Cy-py)*inv;
        float p0x = rbase[idx],        p0y = rbase[HW+idx];
        float p1x = rbase[2*HW+idx],   p1y = rbase[3*HW+idx];
        float p2x = rbase[4*HW+idx],   p2y = rbase[5*HW+idx];
        float p0 = (p0x-g0x)*(p0x-g0x) + (p0y-g0y)*(p0y-g0y);
        float d00 = sqrtf((p1x-g1x)*(p1x-g1x)+(p1y-g1y)*(p1y-g1y));
        float d01 = sqrtf((p1x-g2x)*(p1x-g2x)+(p1y-g2y)*(p1y-g2y));
        float d10 = sqrtf((p2x-g1x)*(p2x-g1x)+(p2y-g1y)*(p2y-g1y));
        float d11 = sqrtf((p2x-g2x)*(p2x-g2x)+(p2y-g2y)*(p2y-g2y));
        float cd = fminf(d00,d01)+fminf(d10,d11)+fminf(d00,d10)+fminf(d01,d11);
        regsum += p0 + cd;            // LAMBDA_P0 = LAMBDA_CD = 1
        clssum += sp(-cbase[idx]);
        cnt++;
        unsigned old = atomicExch(&tbase[idx], ep);
        if (old != ep){
            float x = obase[idx];
            objsum += 1.2f*sp(-x) - sp(x);
            ot++;
        }
    };

    // small region: thresholded only when selection happened within it
    for (int j=tid; j<ns; j+=LBLOCK) acc(j, selS);
    // big region: skipped entirely when selS (all rejected there)
    if (!selS){
        for (int j=tid; j<nb; j+=LBLOCK) acc(CAP-1-j, selB);
    }

    for (int off=16;off;off>>=1){
        regsum += __shfl_xor_sync(FULLMASK,regsum,off);
        clssum += __shfl_xor_sync(FULLMASK,clssum,off);
        objsum += __shfl_xor_sync(FULLMASK,objsum,off);
        cnt    += __shfl_xor_sync(FULLMASK,cnt,off);
        ot     += __shfl_xor_sync(FULLMASK,ot,off);
    }
    if (lane==0 && cnt){
        atomicAdd(&s_reg,regsum); atomicAdd(&s_cls,clssum); atomicAdd(&s_cnt,cnt);
        if (ot){ atomicAdd(&s_obj,objsum); atomicAdd(&s_ot,ot); }
    }
    __syncthreads();
    if (tid==0 && s_cnt){
        atomicAdd(&g_reg,(double)s_reg);
        atomicAdd(&g_cls,(double)s_cls);
        atomicAdd(&g_pc,(unsigned long long)s_cnt);
        if (s_ot){
            atomicAdd(&g_obj,(double)s_obj);
            atomicAdd(&g_objt,(unsigned long long)(unsigned)s_ot);
        }
    }
    finish();
}

extern "C" void kernel_launch(void* const* d_in, const int* in_sizes, int n_in,
                              void* d_out, int out_size)
{
    const float* reg0 = (const float*)d_in[0];
    const float* obj0 = (const float*)d_in[1];
    const float* cls0 = (const float*)d_in[2];
    const float* reg1 = (const float*)d_in[3];
    const float* obj1 = (const float*)d_in[4];
    const float* cls1 = (const float*)d_in[5];
    const float* reg2 = (const float*)d_in[6];
    const float* obj2 = (const float*)d_in[7];
    const float* cls2 = (const float*)d_in[8];
    const float* gt   = (const float*)d_in[9];
    float* out = (float*)d_out;

    const int smem = CAP*4 + 256*4 + CAP*2;   // 56320 bytes
    static int attr_set = 0;
    if (!attr_set){
        cudaFuncSetAttribute(level_all,
            cudaFuncAttributeMaxDynamicSharedMemorySize, smem);
        attr_set = 1;
    }

    level_all<<<TOTAL_BLOCKS,LBLOCK,smem>>>(
        reg0, cls0, reg1, cls1, reg2, cls2, obj0, obj1, obj2, gt, out);
}

// round 12
// speedup vs baseline: 1.1014x; 1.1014x over previous
#include <cuda_runtime.h>
#include <cstdint>

#define FULLMASK 0xffffffffu
#define CAP 9216          // hard upper bound on candidates per (b,g) at L0
#define LBLOCK 512
#define NWARPS (LBLOCK/32)
#define LEVEL_BLOCKS 1536
#define DENSE_BLOCKS 168          // 168*512 = 86016 float4 = 344064 floats
#define TOTAL_BLOCKS (LEVEL_BLOCKS + DENSE_BLOCKS)

// ---------------- global scratch (no allocs allowed) ----------------
__device__ double g_reg, g_cls, g_obj;
__device__ unsigned long long g_pc, g_objt;
__device__ unsigned int g_done;
__device__ unsigned int g_epoch = 1u;
__device__ unsigned int g_tag[344064];

// stable softplus, matches jax.nn.softplus
__device__ __forceinline__ float sp(float x){
    return fmaxf(x, 0.0f) + log1pf(expf(-fabsf(x)));
}

__global__ __launch_bounds__(LBLOCK, 3) void level_all(
    const float* __restrict__ reg0, const float* __restrict__ cls0,
    const float* __restrict__ reg1, const float* __restrict__ cls1,
    const float* __restrict__ reg2, const float* __restrict__ cls2,
    const float* __restrict__ o0,   const float* __restrict__ o1,
    const float* __restrict__ o2,
    const float* __restrict__ gt,
    float* __restrict__ out)
{
    extern __shared__ unsigned int smem_raw[];
    unsigned int*      sdist  = smem_raw;                    // CAP u32
    unsigned int*      sh_hist= smem_raw + CAP;              // 256 u32
    unsigned short*    sidx   = (unsigned short*)(smem_raw + CAP + 256); // CAP u16
    __shared__ unsigned int srow[128];
    __shared__ unsigned int sh_list[96];                      // compacted accepted cells
    __shared__ unsigned int sh_n, sh_sel, sh_newk, sh_selcnt, sh_kd, sh_lcnt;
    __shared__ float s_reg, s_cls, s_obj; __shared__ int s_cnt, s_ot;

    const int tid  = threadIdx.x;
    const int lane = tid & 31;
    const int warpid = tid >> 5;
    const unsigned ep = g_epoch;

    auto finish = [&](){
        __syncthreads();
        if (tid==0){
            __threadfence();
            unsigned ticket = atomicAdd(&g_done, 1u);
            if (ticket == TOTAL_BLOCKS-1){
                double reg = atomicAdd(&g_reg, 0.0);
                double cls = atomicAdd(&g_cls, 0.0);
                double obj = atomicAdd(&g_obj, 0.0);
                double pcv = (double)atomicAdd(&g_pc, 0ull);
                double otv = (double)atomicAdd(&g_objt, 0ull);
                double pc = pcv < 1.0 ? 1.0 : pcv;
                double nc = 344064.0 - otv; if (nc < 1.0) nc = 1.0;
                out[0] = (float)(reg/pc + obj/(pc+nc) + cls/pc);
                g_reg = 0.0; g_cls = 0.0; g_obj = 0.0;
                g_pc = 0ull; g_objt = 0ull;
                g_epoch = ep + 1u;
                __threadfence();
                g_done = 0u;
            }
        }
    };

    // ---------- dense obj blocks (tail-filling) ----------
    if (blockIdx.x >= LEVEL_BLOCKS){
        int v = (blockIdx.x - LEVEL_BLOCKS)*LBLOCK + tid;   // < 86016
        int i = v*4;
        const float* p; int local;
        if (i < 262144){ p=o0; local=i; }
        else if (i < 327680){ p=o1; local=i-262144; }
        else { p=o2; local=i-327680; }
        float4 x = *(const float4*)(p + local);
        float sum = sp(x.x)+sp(x.y)+sp(x.z)+sp(x.w);
        for (int off=16;off;off>>=1)
            sum += __shfl_xor_sync(FULLMASK,sum,off);
        __shared__ float s_sum;
        if (tid==0) s_sum = 0.f;
        __syncthreads();
        if (lane==0) atomicAdd(&s_sum, sum);
        __syncthreads();
        if (tid==0) atomicAdd(&g_obj, (double)s_sum);
        finish();
        return;
    }

    const int lv   = blockIdx.x >> 9;
    const int pair = blockIdx.x & 511;
    const int b    = pair >> 5;            // Ng = 32

    int W, logW, lvbase; float stride;
    const float *preg, *pcls, *pobj;
    if (lv==0){ W=128; logW=7; lvbase=0;      stride= 8.f; preg=reg0; pcls=cls0; pobj=o0; }
    else if (lv==1){ W=64; logW=6; lvbase=262144; stride=16.f; preg=reg1; pcls=cls1; pobj=o1; }
    else       { W=32; logW=5; lvbase=327680; stride=32.f; preg=reg2; pcls=cls2; pobj=o2; }
    const int H  = W;
    const int HW = 1 << (2*logW);

    if (tid==0){ sh_n=0; sh_lcnt=0; s_reg=0.f; s_cls=0.f; s_obj=0.f; s_cnt=0; s_ot=0; }
    __syncthreads();

    const float* t = gt + (size_t)pair * 6;
    const float Ax=t[0],Ay=t[1],Bx=t[2],By=t[3],Cx=t[4],Cy=t[5];

    const float c1a = Ay-By, c1b = -(Ax-Bx), c1c = -Bx*(Ay-By) + By*(Ax-Bx);
    const float c2a = By-Cy, c2b = -(Bx-Cx), c2c = -Cx*(By-Cy) + Cy*(Bx-Cx);
    const float c3a = Cy-Ay, c3b = -(Cx-Ax), c3c = -Ax*(Cy-Ay) + Ay*(Cx-Ax);
    const float v0x=Bx-Ax, v0y=By-Ay, r0=1.0f/(v0x*v0x+v0y*v0y+1e-9f);
    const float v1x=Cx-Bx, v1y=Cy-By, r1=1.0f/(v1x*v1x+v1y*v1y+1e-9f);
    const float v2x=Ax-Cx, v2y=Ay-Cy, r2=1.0f/(v2x*v2x+v2y*v2y+1e-9f);

    float xmn = fminf(Ax,fminf(Bx,Cx)) - 3.0f;
    float xmx = fmaxf(Ax,fmaxf(Bx,Cx)) + 3.0f;
    float ymn = fminf(Ay,fminf(By,Cy)) - 3.0f;
    float ymx = fmaxf(Ay,fmaxf(By,Cy)) + 3.0f;
    float inv = 1.0f/stride;
    int w0 = max(0,   (int)floorf(xmn*inv - 0.5f) - 1);
    int w1 = min(W-1, (int)ceilf (xmx*inv - 0.5f) + 1);
    int h0 = max(0,   (int)floorf(ymn*inv - 0.5f) - 1);
    int h1 = min(H-1, (int)ceilf (ymx*inv - 0.5f) + 1);
    int winH = h1 - h0 + 1; if (w1 < w0) winH = 0;

    // ---- phase 0: per-row candidate interval via strip clipping ----
    if (tid < winH){
        float py = (h0+tid+0.5f)*stride;
        float ylo = py - 3.0f, yhi = py + 3.0f;
        float xa = 1e30f, xb = -1e30f;
        auto edge = [&](float Px,float Py,float Qx,float Qy){
            float vy = Qy-Py;
            float t0 = 0.f, t1 = 1.f;
            if (fabsf(vy) > 1e-9f){
                float rv = 1.0f/vy;
                float ta = (ylo-Py)*rv, tb = (yhi-Py)*rv;
                t0 = fmaxf(0.f, fminf(ta,tb));
                t1 = fminf(1.f, fmaxf(ta,tb));
                if (t0 > t1) return;
            } else {
                if (Py < ylo || Py > yhi) return;
            }
            float vx = Qx-Px;
            float x0 = Px + t0*vx, x1 = Px + t1*vx;
            xa = fminf(xa, fminf(x0,x1));
            xb = fmaxf(xb, fmaxf(x0,x1));
        };
        edge(Ax,Ay,Bx,By); edge(Bx,By,Cx,Cy); edge(Cx,Cy,Ax,Ay);
        int clo = w0, ncols = 0;
        if (xb >= xa){
            xa -= 3.0f + stride; xb += 3.0f + stride;
            clo     = (int)floorf(xa*inv - 0.5f) - 1;
            int chi = (int)ceilf (xb*inv - 0.5f) + 1;
            clo = max(clo, w0); chi = min(chi, w1);
            ncols = chi - clo + 1;
            if (ncols < 0){ ncols = 0; clo = w0; }
        }
        srow[tid] = (unsigned)clo | ((unsigned)ncols << 16);
    }
    __syncthreads();

    // ---- phase 1: warp-per-row geometry over candidate intervals ----
    for (int rr = warpid; rr < winH; rr += NWARPS){
        unsigned pk = srow[rr];
        int clo   = pk & 0xFFFFu;
        int ncols = pk >> 16;
        int hh = h0 + rr;
        float py = (hh+0.5f)*stride;
        float d1r = py*c1b + c1c;
        float d2r = py*c2b + c2c;
        float d3r = py*c3b + c3c;
        float wy0 = py-Ay, wy1 = py-By, wy2 = py-Cy;
        float ky0 = wy0*v0y, ky1 = wy1*v1y, ky2 = wy2*v2y;
        for (int c0 = 0; c0 < ncols; c0 += 32){
            int cc = c0 + lane;
            bool valid = cc < ncols;
            int ww = clo + cc;
            unsigned int dv = 0, iv = 0; bool cand = false;
            if (valid){
                float px = (ww+0.5f)*stride;
                float d1 = px*c1a + d1r;
                float d2 = px*c2a + d2r;
                float d3 = px*c3a + d3r;
                bool hneg = (d1<0.f)||(d2<0.f)||(d3<0.f);
                bool hpos = (d1>0.f)||(d2>0.f)||(d3>0.f);
                bool inside = !(hneg&&hpos);
                float wx, tt, dx, dy;
                wx=px-Ax; tt=fminf(fmaxf((wx*v0x+ky0)*r0,0.f),1.f);
                dx=wx-tt*v0x; dy=wy0-tt*v0y; float q0=dx*dx+dy*dy;
                wx=px-Bx; tt=fminf(fmaxf((wx*v1x+ky1)*r1,0.f),1.f);
                dx=wx-tt*v1x; dy=wy1-tt*v1y; float q1=dx*dx+dy*dy;
                wx=px-Cx; tt=fminf(fmaxf((wx*v2x+ky2)*r2,0.f),1.f);
                dx=wx-tt*v2x; dy=wy2-tt*v2y; float q2=dx*dx+dy*dy;
                float dist = sqrtf(fminf(q0,fminf(q1,q2)) + 1e-12f);
                if (inside || dist<=3.0f){
                    cand = true;
                    dv = __float_as_uint(dist);
                    iv = (unsigned)((hh<<logW)|ww);
                }
            }
            unsigned bal = __ballot_sync(FULLMASK, cand);
            int wc = __popc(bal);
            if (wc){
                unsigned base = 0;
                if (lane==0) base = atomicAdd(&sh_n,(unsigned)wc);
                base = __shfl_sync(FULLMASK, base, 0);
                if (cand){
                    unsigned pos = base + __popc(bal & ((1u<<lane)-1));
                    if (pos < CAP){ sdist[pos]=dv; sidx[pos]=(unsigned short)iv; }
                }
            }
        }
    }
    __syncthreads();
    const int n = min((int)sh_n, CAP);
    const bool accept_all = (n <= 96);

    // warp-0 scan+pick over 256 bins; writes sh_sel/sh_newk/sh_selcnt
    auto scanpick = [&](int k){
        if (tid < 32){
            unsigned v[8]; unsigned run=0;
            #pragma unroll
            for (int u=0;u<8;u++){ run += sh_hist[lane*8+u]; v[u]=run; }
            unsigned p = run;
            #pragma unroll
            for (int off=1;off<32;off<<=1){
                unsigned nn = __shfl_up_sync(FULLMASK,p,off);
                if (lane>=off) p += nn;
            }
            unsigned excl = p - run;
            #pragma unroll
            for (int u=0;u<8;u++){
                unsigned cum  = excl + v[u];
                unsigned prev = excl + (u? v[u-1] : 0u);
                if (cum >= (unsigned)k && prev < (unsigned)k){
                    sh_sel = lane*8+u; sh_newk = k - prev; sh_selcnt = cum - prev;
                }
            }
        }
    };

    // ---- phase 2: radix select of 96th smallest (dist, then idx tiebreak) ----
    unsigned int D  = 0xFFFFFFFFu;
    unsigned int Ti = 0xFFFFu;
    if (!accept_all){
        unsigned pref = 0;
        int k = 96;
        bool done = false;
        for (int shift=24; shift>=0 && !done; shift-=8){
            if (tid < 256) sh_hist[tid] = 0;
            __syncthreads();
            for (int j0=0; j0<n; j0+=LBLOCK){
                int j = j0 + tid;
                unsigned bin = 0xFFFFFFFFu;
                if (j < n){
                    unsigned dv = sdist[j];
                    if (shift==24 || (dv>>(shift+8)) == pref)
                        bin = (dv>>shift)&0xFF;
                }
                unsigned mm = __match_any_sync(FULLMASK, bin);
                if (bin != 0xFFFFFFFFu && lane == (__ffs(mm)-1))
                    atomicAdd(&sh_hist[bin], (unsigned)__popc(mm));
            }
            __syncthreads();
            scanpick(k);
            __syncthreads();
            unsigned sel = sh_sel; k = (int)sh_newk; unsigned ceq = sh_selcnt;
            pref = (pref<<8) | sel;
            if (ceq == 1u){
                for (int j=tid; j<n; j+=LBLOCK)
                    if ((sdist[j]>>shift) == pref) sh_kd = sdist[j];
                __syncthreads();
                D = sh_kd;
                done = true;
            } else if (shift==0){
                D = pref;
                if ((unsigned)k != ceq){
                    unsigned ipref = 0;
                    for (int s2_=8; s2_>=0; s2_-=8){
                        __syncthreads();
                        if (tid < 256) sh_hist[tid] = 0;
                        __syncthreads();
                        for (int j0=0; j0<n; j0+=LBLOCK){
                            int j = j0 + tid;
                            unsigned bin = 0xFFFFFFFFu;
                            if (j < n && sdist[j] == D){
                                unsigned ivv = sidx[j];
                                if (s2_==8 || (ivv>>8) == ipref)
                                    bin = (ivv>>s2_)&0xFF;
                            }
                            unsigned mm = __match_any_sync(FULLMASK, bin);
                            if (bin != 0xFFFFFFFFu && lane == (__ffs(mm)-1))
                                atomicAdd(&sh_hist[bin], (unsigned)__popc(mm));
                        }
                        __syncthreads();
                        scanpick(k);
                        __syncthreads();
                        ipref = (ipref<<8) | sh_sel; k = (int)sh_newk;
                    }
                    Ti = ipref;
                }
                done = true;
            }
        }
    }

    // ---- phase 3a: compact accepted candidates (exactly <=96) into sh_list ----
    for (int j0=0; j0<n; j0+=LBLOCK){
        int j = j0 + tid;
        bool ok = false; unsigned ivv = 0;
        if (j < n){
            unsigned dv = sdist[j];
            ivv = sidx[j];
            ok = accept_all || (dv < D) || (dv == D && ivv <= Ti);
        }
        unsigned bal = __ballot_sync(FULLMASK, ok);
        int wc = __popc(bal);
        if (wc){
            unsigned base = 0;
            if (lane==0) base = atomicAdd(&sh_lcnt,(unsigned)wc);
            base = __shfl_sync(FULLMASK, base, 0);
            if (ok){
                unsigned pos = base + __popc(bal & ((1u<<lane)-1));
                if (pos < 96u) sh_list[pos] = ivv;
            }
        }
    }
    __syncthreads();
    const int m = min((int)sh_lcnt, 96);

    // ---- phase 3b: single full-parallel wave over accepted cells ----
    float regsum=0.f, clssum=0.f, objsum=0.f; int cnt=0, ot=0;
    const float* rbase = preg + (size_t)b*6*HW;
    const float* cbase = pcls + (size_t)b*HW;
    const float* obase = pobj + (size_t)b*HW;
    unsigned int* tbase = g_tag + lvbase + b*HW;
    if (tid < m){
        int idx = (int)sh_list[tid];
        int hh = idx >> logW, ww = idx & (W-1);
        float px=(ww+0.5f)*stride, py=(hh+0.5f)*stride;
        float g0x=(Ax-px)*inv, g0y=(Ay-py)*inv;
        float g1x=(Bx-px)*inv, g1y=(By-py)*inv;
        float g2x=(Cx-px)*inv, g2y=(Cy-py)*inv;
        float p0x = rbase[idx],        p0y = rbase[HW+idx];
        float p1x = rbase[2*HW+idx],   p1y = rbase[3*HW+idx];
        float p2x = rbase[4*HW+idx],   p2y = rbase[5*HW+idx];
        float p0 = (p0x-g0x)*(p0x-g0x) + (p0y-g0y)*(p0y-g0y);
        float d00 = sqrtf((p1x-g1x)*(p1x-g1x)+(p1y-g1y)*(p1y-g1y));
        float d01 = sqrtf((p1x-g2x)*(p1x-g2x)+(p1y-g2y)*(p1y-g2y));
        float d10 = sqrtf((p2x-g1x)*(p2x-g1x)+(p2y-g1y)*(p2y-g1y));
        float d11 = sqrtf((p2x-g2x)*(p2x-g2x)+(p2y-g2y)*(p2y-g2y));
        float cd = fminf(d00,d01)+fminf(d10,d11)+fminf(d00,d10)+fminf(d01,d11);
        regsum = p0 + cd;             // LAMBDA_P0 = LAMBDA_CD = 1
        clssum = sp(-cbase[idx]);
        cnt = 1;
        unsigned old = atomicExch(&tbase[idx], ep);
        if (old != ep){
            float x = obase[idx];
            objsum = 1.2f*sp(-x) - sp(x);
            ot = 1;
        }
    }
    for (int off=16;off;off>>=1){
        regsum += __shfl_xor_sync(FULLMASK,regsum,off);
        clssum += __shfl_xor_sync(FULLMASK,clssum,off);
        objsum += __shfl_xor_sync(FULLMASK,objsum,off);
        cnt    += __shfl_xor_sync(FULLMASK,cnt,off);
        ot     += __shfl_xor_sync(FULLMASK,ot,off);
    }
    if (lane==0 && cnt){
        atomicAdd(&s_reg,regsum); atomicAdd(&s_cls,clssum); atomicAdd(&s_cnt,cnt);
        if (ot){ atomicAdd(&s_obj,objsum); atomicAdd(&s_ot,ot); }
    }
    __syncthreads();
    if (tid==0 && s_cnt){
        atomicAdd(&g_reg,(double)s_reg);
        atomicAdd(&g_cls,(double)s_cls);
        atomicAdd(&g_pc,(unsigned long long)s_cnt);
        if (s_ot){
            atomicAdd(&g_obj,(double)s_obj);
            atomicAdd(&g_objt,(unsigned long long)(unsigned)s_ot);
        }
    }
    finish();
}

extern "C" void kernel_launch(void* const* d_in, const int* in_sizes, int n_in,
                              void* d_out, int out_size)
{
    const float* reg0 = (const float*)d_in[0];
    const float* obj0 = (const float*)d_in[1];
    const float* cls0 = (const float*)d_in[2];
    const float* reg1 = (const float*)d_in[3];
    const float* obj1 = (const float*)d_in[4];
    const float* cls1 = (const float*)d_in[5];
    const float* reg2 = (const float*)d_in[6];
    const float* obj2 = (const float*)d_in[7];
    const float* cls2 = (const float*)d_in[8];
    const float* gt   = (const float*)d_in[9];
    float* out = (float*)d_out;

    const int smem = CAP*4 + 256*4 + CAP*2;   // 56320 bytes
    static int attr_set = 0;
    if (!attr_set){
        cudaFuncSetAttribute(level_all,
            cudaFuncAttributeMaxDynamicSharedMemorySize, smem);
        attr_set = 1;
    }

    level_all<<<TOTAL_BLOCKS,LBLOCK,smem>>>(
        reg0, cls0, reg1, cls1, reg2, cls2, obj0, obj1, obj2, gt, out);
}

// round 13
// speedup vs baseline: 1.1560x; 1.0496x over previous
#include <cuda_runtime.h>
#include <cstdint>

#define FULLMASK 0xffffffffu
#define CAP 9216          // hard upper bound on candidates per (b,g) at L0
#define LBLOCK 512
#define NWARPS (LBLOCK/32)
#define LEVEL_BLOCKS 1536
#define DENSE_BLOCKS 168          // 168*512 = 86016 float4 = 344064 floats
#define TOTAL_BLOCKS (LEVEL_BLOCKS + DENSE_BLOCKS)

// ---------------- global scratch (no allocs allowed) ----------------
__device__ double g_reg, g_cls, g_obj;
__device__ unsigned long long g_pc, g_objt;
__device__ unsigned int g_done;
__device__ unsigned int g_epoch = 1u;
__device__ unsigned int g_tag[344064];

// stable softplus, matches jax.nn.softplus
__device__ __forceinline__ float sp(float x){
    return fmaxf(x, 0.0f) + log1pf(expf(-fabsf(x)));
}

__global__ __launch_bounds__(LBLOCK, 3) void level_all(
    const float* __restrict__ reg0, const float* __restrict__ cls0,
    const float* __restrict__ reg1, const float* __restrict__ cls1,
    const float* __restrict__ reg2, const float* __restrict__ cls2,
    const float* __restrict__ o0,   const float* __restrict__ o1,
    const float* __restrict__ o2,
    const float* __restrict__ gt,
    float* __restrict__ out)
{
    extern __shared__ unsigned int smem_raw[];
    unsigned int*      sdist  = smem_raw;                    // CAP u32 (squared-dist bits)
    unsigned int*      sh_hist= smem_raw + CAP;              // 256 u32
    unsigned short*    sidx   = (unsigned short*)(smem_raw + CAP + 256); // CAP u16
    __shared__ unsigned int srow[128];
    __shared__ unsigned int sh_list[96];                      // compacted accepted cells
    __shared__ unsigned int sh_n, sh_sel, sh_newk, sh_selcnt, sh_kd, sh_lcnt;
    __shared__ float s_reg, s_cls, s_obj; __shared__ int s_cnt, s_ot;

    const int tid  = threadIdx.x;
    const int lane = tid & 31;
    const int warpid = tid >> 5;
    const unsigned ep = g_epoch;

    auto finish = [&](){
        __syncthreads();
        if (tid==0){
            __threadfence();
            unsigned ticket = atomicAdd(&g_done, 1u);
            if (ticket == TOTAL_BLOCKS-1){
                double reg = atomicAdd(&g_reg, 0.0);
                double cls = atomicAdd(&g_cls, 0.0);
                double obj = atomicAdd(&g_obj, 0.0);
                double pcv = (double)atomicAdd(&g_pc, 0ull);
                double otv = (double)atomicAdd(&g_objt, 0ull);
                double pc = pcv < 1.0 ? 1.0 : pcv;
                double nc = 344064.0 - otv; if (nc < 1.0) nc = 1.0;
                out[0] = (float)(reg/pc + obj/(pc+nc) + cls/pc);
                g_reg = 0.0; g_cls = 0.0; g_obj = 0.0;
                g_pc = 0ull; g_objt = 0ull;
                g_epoch = ep + 1u;
                __threadfence();
                g_done = 0u;
            }
        }
    };

    // ---------- dense obj blocks (tail-filling) ----------
    if (blockIdx.x >= LEVEL_BLOCKS){
        int v = (blockIdx.x - LEVEL_BLOCKS)*LBLOCK + tid;   // < 86016
        int i = v*4;
        const float* p; int local;
        if (i < 262144){ p=o0; local=i; }
        else if (i < 327680){ p=o1; local=i-262144; }
        else { p=o2; local=i-327680; }
        float4 x = *(const float4*)(p + local);
        float sum = sp(x.x)+sp(x.y)+sp(x.z)+sp(x.w);
        for (int off=16;off;off>>=1)
            sum += __shfl_xor_sync(FULLMASK,sum,off);
        __shared__ float s_sum;
        if (tid==0) s_sum = 0.f;
        __syncthreads();
        if (lane==0) atomicAdd(&s_sum, sum);
        __syncthreads();
        if (tid==0) atomicAdd(&g_obj, (double)s_sum);
        finish();
        return;
    }

    const int lv   = blockIdx.x >> 9;
    const int pair = blockIdx.x & 511;
    const int b    = pair >> 5;            // Ng = 32

    int W, logW, lvbase; float stride;
    const float *preg, *pcls, *pobj;
    if (lv==0){ W=128; logW=7; lvbase=0;      stride= 8.f; preg=reg0; pcls=cls0; pobj=o0; }
    else if (lv==1){ W=64; logW=6; lvbase=262144; stride=16.f; preg=reg1; pcls=cls1; pobj=o1; }
    else       { W=32; logW=5; lvbase=327680; stride=32.f; preg=reg2; pcls=cls2; pobj=o2; }
    const int H  = W;
    const int HW = 1 << (2*logW);

    if (tid==0){ sh_n=0; sh_lcnt=0; s_reg=0.f; s_cls=0.f; s_obj=0.f; s_cnt=0; s_ot=0; }
    __syncthreads();

    const float* t = gt + (size_t)pair * 6;
    const float Ax=t[0],Ay=t[1],Bx=t[2],By=t[3],Cx=t[4],Cy=t[5];

    const float c1a = Ay-By, c1b = -(Ax-Bx), c1c = -Bx*(Ay-By) + By*(Ax-Bx);
    const float c2a = By-Cy, c2b = -(Bx-Cx), c2c = -Cx*(By-Cy) + Cy*(Bx-Cx);
    const float c3a = Cy-Ay, c3b = -(Cx-Ax), c3c = -Ax*(Cy-Ay) + Ay*(Cx-Ax);
    const float v0x=Bx-Ax, v0y=By-Ay, r0=1.0f/(v0x*v0x+v0y*v0y+1e-9f);
    const float v1x=Cx-Bx, v1y=Cy-By, r1=1.0f/(v1x*v1x+v1y*v1y+1e-9f);
    const float v2x=Ax-Cx, v2y=Ay-Cy, r2=1.0f/(v2x*v2x+v2y*v2y+1e-9f);

    float xmn = fminf(Ax,fminf(Bx,Cx)) - 3.0f;
    float xmx = fmaxf(Ax,fmaxf(Bx,Cx)) + 3.0f;
    float ymn = fminf(Ay,fminf(By,Cy)) - 3.0f;
    float ymx = fmaxf(Ay,fmaxf(By,Cy)) + 3.0f;
    float inv = 1.0f/stride;
    int w0 = max(0,   (int)floorf(xmn*inv - 0.5f) - 1);
    int w1 = min(W-1, (int)ceilf (xmx*inv - 0.5f) + 1);
    int h0 = max(0,   (int)floorf(ymn*inv - 0.5f) - 1);
    int h1 = min(H-1, (int)ceilf (ymx*inv - 0.5f) + 1);
    int winH = h1 - h0 + 1; if (w1 < w0) winH = 0;

    // ---- phase 0: per-row candidate interval via strip clipping ----
    if (tid < winH){
        float py = (h0+tid+0.5f)*stride;
        float ylo = py - 3.0f, yhi = py + 3.0f;
        float xa = 1e30f, xb = -1e30f;
        auto edge = [&](float Px,float Py,float Qx,float Qy){
            float vy = Qy-Py;
            float t0 = 0.f, t1 = 1.f;
            if (fabsf(vy) > 1e-9f){
                float rv = 1.0f/vy;
                float ta = (ylo-Py)*rv, tb = (yhi-Py)*rv;
                t0 = fmaxf(0.f, fminf(ta,tb));
                t1 = fminf(1.f, fmaxf(ta,tb));
                if (t0 > t1) return;
            } else {
                if (Py < ylo || Py > yhi) return;
            }
            float vx = Qx-Px;
            float x0 = Px + t0*vx, x1 = Px + t1*vx;
            xa = fminf(xa, fminf(x0,x1));
            xb = fmaxf(xb, fmaxf(x0,x1));
        };
        edge(Ax,Ay,Bx,By); edge(Bx,By,Cx,Cy); edge(Cx,Cy,Ax,Ay);
        int clo = w0, ncols = 0;
        if (xb >= xa){
            xa -= 3.0f + stride; xb += 3.0f + stride;
            clo     = (int)floorf(xa*inv - 0.5f) - 1;
            int chi = (int)ceilf (xb*inv - 0.5f) + 1;
            clo = max(clo, w0); chi = min(chi, w1);
            ncols = chi - clo + 1;
            if (ncols < 0){ ncols = 0; clo = w0; }
        }
        srow[tid] = (unsigned)clo | ((unsigned)ncols << 16);
    }
    __syncthreads();

    // ---- phase 1: warp-per-row geometry; rank key = SQUARED distance bits.
    //      (sqrt removed from the hot loop: ordering by s == ordering by
    //       sqrt(s); band test s<=9 with +2e-6 guard for rounding parity)
    for (int rr = warpid; rr < winH; rr += NWARPS){
        unsigned pk = srow[rr];
        int clo   = pk & 0xFFFFu;
        int ncols = pk >> 16;
        int hh = h0 + rr;
        float py = (hh+0.5f)*stride;
        float d1r = py*c1b + c1c;
        float d2r = py*c2b + c2c;
        float d3r = py*c3b + c3c;
        float wy0 = py-Ay, wy1 = py-By, wy2 = py-Cy;
        float ky0 = wy0*v0y, ky1 = wy1*v1y, ky2 = wy2*v2y;
        for (int c0 = 0; c0 < ncols; c0 += 32){
            int cc = c0 + lane;
            bool valid = cc < ncols;
            int ww = clo + cc;
            unsigned int dv = 0, iv = 0; bool cand = false;
            if (valid){
                float px = (ww+0.5f)*stride;
                float d1 = px*c1a + d1r;
                float d2 = px*c2a + d2r;
                float d3 = px*c3a + d3r;
                bool hneg = (d1<0.f)||(d2<0.f)||(d3<0.f);
                bool hpos = (d1>0.f)||(d2>0.f)||(d3>0.f);
                bool inside = !(hneg&&hpos);
                float wx, tt, dx, dy;
                wx=px-Ax; tt=fminf(fmaxf((wx*v0x+ky0)*r0,0.f),1.f);
                dx=wx-tt*v0x; dy=wy0-tt*v0y; float q0=dx*dx+dy*dy;
                wx=px-Bx; tt=fminf(fmaxf((wx*v1x+ky1)*r1,0.f),1.f);
                dx=wx-tt*v1x; dy=wy1-tt*v1y; float q1=dx*dx+dy*dy;
                wx=px-Cx; tt=fminf(fmaxf((wx*v2x+ky2)*r2,0.f),1.f);
                dx=wx-tt*v2x; dy=wy2-tt*v2y; float q2=dx*dx+dy*dy;
                float s = fminf(q0,fminf(q1,q2)) + 1e-12f;
                if (inside || s <= 9.000002f){
                    cand = true;
                    dv = __float_as_uint(s);
                    iv = (unsigned)((hh<<logW)|ww);
                }
            }
            unsigned bal = __ballot_sync(FULLMASK, cand);
            int wc = __popc(bal);
            if (wc){
                unsigned base = 0;
                if (lane==0) base = atomicAdd(&sh_n,(unsigned)wc);
                base = __shfl_sync(FULLMASK, base, 0);
                if (cand){
                    unsigned pos = base + __popc(bal & ((1u<<lane)-1));
                    if (pos < CAP){ sdist[pos]=dv; sidx[pos]=(unsigned short)iv; }
                }
            }
        }
    }
    __syncthreads();
    const int n = min((int)sh_n, CAP);
    const bool accept_all = (n <= 96);

    // warp-0 scan+pick over 256 bins; writes sh_sel/sh_newk/sh_selcnt
    auto scanpick = [&](int k){
        if (tid < 32){
            unsigned v[8]; unsigned run=0;
            #pragma unroll
            for (int u=0;u<8;u++){ run += sh_hist[lane*8+u]; v[u]=run; }
            unsigned p = run;
            #pragma unroll
            for (int off=1;off<32;off<<=1){
                unsigned nn = __shfl_up_sync(FULLMASK,p,off);
                if (lane>=off) p += nn;
            }
            unsigned excl = p - run;
            #pragma unroll
            for (int u=0;u<8;u++){
                unsigned cum  = excl + v[u];
                unsigned prev = excl + (u? v[u-1] : 0u);
                if (cum >= (unsigned)k && prev < (unsigned)k){
                    sh_sel = lane*8+u; sh_newk = k - prev; sh_selcnt = cum - prev;
                }
            }
        }
    };

    // ---- phase 2: radix select of 96th smallest (s-bits, then idx tiebreak) ----
    unsigned int D  = 0xFFFFFFFFu;
    unsigned int Ti = 0xFFFFu;
    if (!accept_all){
        unsigned pref = 0;
        int k = 96;
        bool done = false;
        for (int shift=24; shift>=0 && !done; shift-=8){
            if (tid < 256) sh_hist[tid] = 0;
            __syncthreads();
            for (int j0=0; j0<n; j0+=LBLOCK){
                int j = j0 + tid;
                unsigned bin = 0xFFFFFFFFu;
                if (j < n){
                    unsigned dv = sdist[j];
                    if (shift==24 || (dv>>(shift+8)) == pref)
                        bin = (dv>>shift)&0xFF;
                }
                unsigned mm = __match_any_sync(FULLMASK, bin);
                if (bin != 0xFFFFFFFFu && lane == (__ffs(mm)-1))
                    atomicAdd(&sh_hist[bin], (unsigned)__popc(mm));
            }
            __syncthreads();
            scanpick(k);
            __syncthreads();
            unsigned sel = sh_sel; k = (int)sh_newk; unsigned ceq = sh_selcnt;
            pref = (pref<<8) | sel;
            if (ceq == 1u){
                for (int j=tid; j<n; j+=LBLOCK)
                    if ((sdist[j]>>shift) == pref) sh_kd = sdist[j];
                __syncthreads();
                D = sh_kd;
                done = true;
            } else if (shift==0){
                D = pref;
                if ((unsigned)k != ceq){
                    unsigned ipref = 0;
                    for (int s2_=8; s2_>=0; s2_-=8){
                        __syncthreads();
                        if (tid < 256) sh_hist[tid] = 0;
                        __syncthreads();
                        for (int j0=0; j0<n; j0+=LBLOCK){
                            int j = j0 + tid;
                            unsigned bin = 0xFFFFFFFFu;
                            if (j < n && sdist[j] == D){
                                unsigned ivv = sidx[j];
                                if (s2_==8 || (ivv>>8) == ipref)
                                    bin = (ivv>>s2_)&0xFF;
                            }
                            unsigned mm = __match_any_sync(FULLMASK, bin);
                            if (bin != 0xFFFFFFFFu && lane == (__ffs(mm)-1))
                                atomicAdd(&sh_hist[bin], (unsigned)__popc(mm));
                        }
                        __syncthreads();
                        scanpick(k);
                        __syncthreads();
                        ipref = (ipref<<8) | sh_sel; k = (int)sh_newk;
                    }
                    Ti = ipref;
                }
                done = true;
            }
        }
    }

    // ---- phase 3a: compact accepted candidates (exactly <=96) into sh_list ----
    for (int j0=0; j0<n; j0+=LBLOCK){
        int j = j0 + tid;
        bool ok = false; unsigned ivv = 0;
        if (j < n){
            unsigned dv = sdist[j];
            ivv = sidx[j];
            ok = accept_all || (dv < D) || (dv == D && ivv <= Ti);
        }
        unsigned bal = __ballot_sync(FULLMASK, ok);
        int wc = __popc(bal);
        if (wc){
            unsigned base = 0;
            if (lane==0) base = atomicAdd(&sh_lcnt,(unsigned)wc);
            base = __shfl_sync(FULLMASK, base, 0);
            if (ok){
                unsigned pos = base + __popc(bal & ((1u<<lane)-1));
                if (pos < 96u) sh_list[pos] = ivv;
            }
        }
    }
    __syncthreads();
    const int m = min((int)sh_lcnt, 96);

    // ---- phase 3b: single full-parallel wave over accepted cells ----
    float regsum=0.f, clssum=0.f, objsum=0.f; int cnt=0, ot=0;
    const float* rbase = preg + (size_t)b*6*HW;
    const float* cbase = pcls + (size_t)b*HW;
    const float* obase = pobj + (size_t)b*HW;
    unsigned int* tbase = g_tag + lvbase + b*HW;
    if (tid < m){
        int idx = (int)sh_list[tid];
        int hh = idx >> logW, ww = idx & (W-1);
        float px=(ww+0.5f)*stride, py=(hh+0.5f)*stride;
        float g0x=(Ax-px)*inv, g0y=(Ay-py)*inv;
        float g1x=(Bx-px)*inv, g1y=(By-py)*inv;
        float g2x=(Cx-px)*inv, g2y=(Cy-py)*inv;
        float p0x = rbase[idx],        p0y = rbase[HW+idx];
        float p1x = rbase[2*HW+idx],   p1y = rbase[3*HW+idx];
        float p2x = rbase[4*HW+idx],   p2y = rbase[5*HW+idx];
        float p0 = (p0x-g0x)*(p0x-g0x) + (p0y-g0y)*(p0y-g0y);
        float d00 = sqrtf((p1x-g1x)*(p1x-g1x)+(p1y-g1y)*(p1y-g1y));
        float d01 = sqrtf((p1x-g2x)*(p1x-g2x)+(p1y-g2y)*(p1y-g2y));
        float d10 = sqrtf((p2x-g1x)*(p2x-g1x)+(p2y-g1y)*(p2y-g1y));
        float d11 = sqrtf((p2x-g2x)*(p2x-g2x)+(p2y-g2y)*(p2y-g2y));
        float cd = fminf(d00,d01)+fminf(d10,d11)+fminf(d00,d10)+fminf(d01,d11);
        regsum = p0 + cd;             // LAMBDA_P0 = LAMBDA_CD = 1
        clssum = sp(-cbase[idx]);
        cnt = 1;
        unsigned old = atomicExch(&tbase[idx], ep);
        if (old != ep){
            float x = obase[idx];
            objsum = 1.2f*sp(-x) - sp(x);
            ot = 1;
        }
    }
    for (int off=16;off;off>>=1){
        regsum += __shfl_xor_sync(FULLMASK,regsum,off);
        clssum += __shfl_xor_sync(FULLMASK,clssum,off);
        objsum += __shfl_xor_sync(FULLMASK,objsum,off);
        cnt    += __shfl_xor_sync(FULLMASK,cnt,off);
        ot     += __shfl_xor_sync(FULLMASK,ot,off);
    }
    if (lane==0 && cnt){
        atomicAdd(&s_reg,regsum); atomicAdd(&s_cls,clssum); atomicAdd(&s_cnt,cnt);
        if (ot){ atomicAdd(&s_obj,objsum); atomicAdd(&s_ot,ot); }
    }
    __syncthreads();
    if (tid==0 && s_cnt){
        atomicAdd(&g_reg,(double)s_reg);
        atomicAdd(&g_cls,(double)s_cls);
        atomicAdd(&g_pc,(unsigned long long)s_cnt);
        if (s_ot){
            atomicAdd(&g_obj,(double)s_obj);
            atomicAdd(&g_objt,(unsigned long long)(unsigned)s_ot);
        }
    }
    finish();
}

extern "C" void kernel_launch(void* const* d_in, const int* in_sizes, int n_in,
                              void* d_out, int out_size)
{
    const float* reg0 = (const float*)d_in[0];
    const float* obj0 = (const float*)d_in[1];
    const float* cls0 = (const float*)d_in[2];
    const float* reg1 = (const float*)d_in[3];
    const float* obj1 = (const float*)d_in[4];
    const float* cls1 = (const float*)d_in[5];
    const float* reg2 = (const float*)d_in[6];
    const float* obj2 = (const float*)d_in[7];
    const float* cls2 = (const float*)d_in[8];
    const float* gt   = (const float*)d_in[9];
    float* out = (float*)d_out;

    const int smem = CAP*4 + 256*4 + CAP*2;   // 56320 bytes
    static int attr_set = 0;
    if (!attr_set){
        cudaFuncSetAttribute(level_all,
            cudaFuncAttributeMaxDynamicSharedMemorySize, smem);
        attr_set = 1;
    }

    level_all<<<TOTAL_BLOCKS,LBLOCK,smem>>>(
        reg0, cls0, reg1, cls1, reg2, cls2, obj0, obj1, obj2, gt, out);
}